// round 13
// baseline (speedup 1.0000x reference)
#include <cuda_runtime.h>
#include <cuda_fp16.h>
#include <math.h>
#include <stdint.h>

#define L_SEQ 2048
#define D_MODEL 768
#define D_INNER 1536
#define E2 3072
#define DS 16
#define DR 48
#define XD 80
#define BSZ 2
#define NCH 16
#define CHL 128
#define NTOK 4096

// ---------------- scratch ----------------
__device__ float g_xz[NTOK * E2];                   // [token][e]
__device__ float g_xdbl[2][BSZ * XD * L_SEQ];       // [br][b][k][l]
__device__ float g_dtr[2][NTOK * D_INNER * 2];      // [tok][d] -> {dt, exp(-dt)} interleaved
__device__ float g_hfin[2 * BSZ * D_INNER * NCH * DS];
__device__ float g_P[2 * BSZ * D_INNER * NCH * DS];
__device__ float g_Hinit[2 * BSZ * D_INNER * NCH * DS];
__device__ float g_acc[2][NTOK * D_INNER];          // token-major

// fp16 planes
__device__ uint16_t g_hidH[NTOK * D_MODEL];
__device__ uint16_t g_WinH[E2 * D_MODEL];
__device__ uint16_t g_WoutH[D_MODEL * D_INNER];
__device__ uint16_t g_midH[NTOK * D_INNER];
__device__ uint16_t g_WxH[2][128 * D_INNER];
__device__ uint16_t g_WdtH[2][D_INNER * 64];
__device__ uint16_t g_xcT[2][NTOK * D_INNER];       // conv+silu, token-major fp16
__device__ uint16_t g_dtloH[2][NTOK * 64];
__device__ uint16_t g_szH[NTOK * D_INNER];          // silu(z), token-major fp16

__device__ __forceinline__ float siluf(float v) {
    return v * (1.f / (1.f + __expf(-v)));
}
__device__ __forceinline__ uint16_t h16(float x) { return __half_as_ushort(__float2half(x)); }

// ---------------- pack kernels ----------------
__global__ __launch_bounds__(256) void k_packh3(const float4* __restrict__ s0, ushort4* __restrict__ d0, int n0,
                                                const float4* __restrict__ s1, ushort4* __restrict__ d1, int n1,
                                                const float4* __restrict__ s2, ushort4* __restrict__ d2, int n2) {
    int i = blockIdx.x * blockDim.x + threadIdx.x;
    const float4* s;
    ushort4* d;
    if (i < n0) { s = s0 + i; d = d0 + i; }
    else if (i < n0 + n1) { s = s1 + (i - n0); d = d1 + (i - n0); }
    else if (i < n0 + n1 + n2) { s = s2 + (i - n0 - n1); d = d2 + (i - n0 - n1); }
    else return;
    float4 v = *s;
    ushort4 o;
    o.x = h16(v.x); o.y = h16(v.y); o.z = h16(v.z); o.w = h16(v.w);
    *d = o;
}
__global__ __launch_bounds__(256) void k_packWx(const float* __restrict__ Wx, const float* __restrict__ Wxb) {
    int id = blockIdx.x * blockDim.x + threadIdx.x;
    if (id >= 2 * 128 * D_INNER) return;
    int br = id / (128 * D_INNER);
    int rem = id - br * 128 * D_INNER;
    int m = rem / D_INNER, k = rem - m * D_INNER;
    const float* W = br ? Wxb : Wx;
    g_WxH[br][rem] = (m < XD) ? h16(W[m * D_INNER + k]) : (uint16_t)0;
}
__global__ __launch_bounds__(256) void k_packWdt(const float* __restrict__ Wdt, const float* __restrict__ Wdtb) {
    int id = blockIdx.x * blockDim.x + threadIdx.x;
    if (id >= 2 * D_INNER * 64) return;
    int br = id / (D_INNER * 64);
    int rem = id - br * D_INNER * 64;
    int m = rem >> 6, k = rem & 63;
    const float* W = br ? Wdtb : Wdt;
    g_WdtH[br][rem] = (k < DR) ? h16(W[m * DR + k]) : (uint16_t)0;
}

// ---------------- silu(z) precompute: fp16 [tok][d] ----------------
__global__ __launch_bounds__(256) void k_silz() {
    int i4 = blockIdx.x * blockDim.x + threadIdx.x;
    const int DV = D_INNER / 4;
    if (i4 >= NTOK * DV) return;
    int tok = i4 / DV;
    int d4 = i4 - tok * DV;
    float4 z = *(const float4*)(g_xz + (size_t)tok * E2 + D_INNER + d4 * 4);
    ushort4 o;
    o.x = h16(siluf(z.x)); o.y = h16(siluf(z.y));
    o.z = h16(siluf(z.z)); o.w = h16(siluf(z.w));
    ((ushort4*)g_szH)[i4] = o;
}

// ---------------- tensor-core GEMM: single-pass fp16 ----------------
#define LDSM4(R, addr) \
    asm volatile("ldmatrix.sync.aligned.m8n8.x4.shared.b16 {%0,%1,%2,%3},[%4];" \
                 : "=r"(R[0]), "=r"(R[1]), "=r"(R[2]), "=r"(R[3]) : "r"(addr))

#define MMA16816(c, a, b0_, b1_) \
    asm volatile("mma.sync.aligned.m16n8k16.row.col.f32.f16.f16.f32 " \
                 "{%0,%1,%2,%3},{%4,%5,%6,%7},{%8,%9},{%0,%1,%2,%3};" \
                 : "+f"(c[0]), "+f"(c[1]), "+f"(c[2]), "+f"(c[3]) \
                 : "r"(a[0]), "r"(a[1]), "r"(a[2]), "r"(a[3]), "r"(b0_), "r"(b1_))

#define GEMM_DECL_SMEM() \
    __shared__ __align__(16) uint16_t Ash[2][128][24]; \
    __shared__ __align__(16) uint16_t Bsh[2][128][24]

#define GEMM_THREAD_IDS() \
    const int tid = threadIdx.x; \
    const int lane = tid & 31, wid = tid >> 5; \
    const int wm = wid >> 2, wn = wid & 3; \
    const int arow = tid >> 1, aseg = tid & 1

#define GEMM_ACC_INIT() \
    float acc[4][4][4]; \
    _Pragma("unroll") for (int i = 0; i < 4; i++) \
    _Pragma("unroll") for (int j = 0; j < 4; j++) \
    _Pragma("unroll") for (int q = 0; q < 4; q++) acc[i][j][q] = 0.f

#define GEMM_MAINLOOP(pA, pB, NK) \
    uint4 ra, rb; \
    ra = *(const uint4*)(pA); \
    rb = *(const uint4*)(pB); \
    *(uint4*)&Ash[0][arow][aseg * 8] = ra; \
    *(uint4*)&Bsh[0][arow][aseg * 8] = rb; \
    __syncthreads(); \
    const int lr = lane & 15, lc = lane >> 4; \
    const int brow = wn * 32 + (lane & 7) + ((lane >> 3) & 1) * 8; \
    int buf = 0; \
    for (int kt = 0; kt < (NK); ++kt) { \
        if (kt + 1 < (NK)) { \
            ra = *(const uint4*)((pA) + (kt + 1) * 16); \
            rb = *(const uint4*)((pB) + (kt + 1) * 16); \
        } \
        uint32_t ah[4][4], bh[2][4]; \
        { \
            uint32_t aB = (uint32_t)__cvta_generic_to_shared(&Ash[buf][wm * 64 + lr][0]) + lc * 16; \
            _Pragma("unroll") for (int mt = 0; mt < 4; mt++) { \
                LDSM4(ah[mt], aB + mt * 16 * 48); \
            } \
            uint32_t bB = (uint32_t)__cvta_generic_to_shared(&Bsh[buf][brow][0]) + lc * 16; \
            _Pragma("unroll") for (int np = 0; np < 2; np++) { \
                LDSM4(bh[np], bB + np * 16 * 48); \
            } \
        } \
        _Pragma("unroll") for (int mt = 0; mt < 4; mt++) { \
            _Pragma("unroll") for (int nt = 0; nt < 4; nt++) { \
                const int np = nt >> 1, sel = nt & 1; \
                MMA16816(acc[mt][nt], ah[mt], bh[np][sel], bh[np][sel + 2]); \
            } \
        } \
        if (kt + 1 < (NK)) { \
            buf ^= 1; \
            *(uint4*)&Ash[buf][arow][aseg * 8] = ra; \
            *(uint4*)&Bsh[buf][arow][aseg * 8] = rb; \
            __syncthreads(); \
        } \
    }

// Row-major C
__global__ __launch_bounds__(256) void k_mma(const uint16_t* __restrict__ Ag,
                                             const uint16_t* __restrict__ Bg,
                                             float* __restrict__ Cg, int K, int ldc) {
    GEMM_DECL_SMEM();
    GEMM_THREAD_IDS();
    const int m0 = blockIdx.y * 128, n0 = blockIdx.x * 128;
    const uint16_t* pA = Ag + (size_t)(m0 + arow) * K + aseg * 8;
    const uint16_t* pB = Bg + (size_t)(n0 + arow) * K + aseg * 8;
    const int NK = K >> 4;
    GEMM_ACC_INIT();
    GEMM_MAINLOOP(pA, pB, NK);

    float* Cbase = Cg + (size_t)m0 * ldc + n0;
#pragma unroll
    for (int mt = 0; mt < 4; mt++) {
        int row = wm * 64 + mt * 16 + (lane >> 2);
#pragma unroll
        for (int nt = 0; nt < 4; nt++) {
            int col = wn * 32 + nt * 8 + (lane & 3) * 2;
            *(float2*)(Cbase + (size_t)row * ldc + col) = make_float2(acc[mt][nt][0], acc[mt][nt][1]);
            *(float2*)(Cbase + (size_t)(row + 8) * ldc + col) = make_float2(acc[mt][nt][2], acc[mt][nt][3]);
        }
    }
}

// x_dbl GEMM: split-K 3, atomic epilogue
__global__ __launch_bounds__(256) void k_gx() {
    GEMM_DECL_SMEM();
    GEMM_THREAD_IDS();
    const int z = blockIdx.z;
    const int br = z / 3, ks = z - br * 3;
    const int k0 = ks * 512;
    const int K = D_INNER;
    const uint16_t* Ag = g_WxH[br];
    const uint16_t* Bg = g_xcT[br];
    const int n0 = blockIdx.x * 128;
    const uint16_t* pA = Ag + (size_t)arow * K + k0 + aseg * 8;
    const uint16_t* pB = Bg + (size_t)(n0 + arow) * K + k0 + aseg * 8;
    const int NK = 32;
    GEMM_ACC_INIT();
    GEMM_MAINLOOP(pA, pB, NK);

    const int b = n0 >> 11;
    const int l0c = n0 & (L_SEQ - 1);
    float* xd = g_xdbl[br] + ((size_t)b * XD) * L_SEQ + l0c;
#pragma unroll
    for (int mt = 0; mt < 4; mt++) {
        int row = wm * 64 + mt * 16 + (lane >> 2);
#pragma unroll
        for (int nt = 0; nt < 4; nt++) {
            int col = wn * 32 + nt * 8 + (lane & 3) * 2;
            if (row < XD) {
                atomicAdd(xd + (size_t)row * L_SEQ + col, acc[mt][nt][0]);
                atomicAdd(xd + (size_t)row * L_SEQ + col + 1, acc[mt][nt][1]);
            }
            if (row + 8 < XD) {
                atomicAdd(xd + (size_t)(row + 8) * L_SEQ + col, acc[mt][nt][2]);
                atomicAdd(xd + (size_t)(row + 8) * L_SEQ + col + 1, acc[mt][nt][3]);
            }
        }
    }
}

// dt GEMM: epilogue computes dt = softplus(v) AND r = exp(-dt) = 1/(1+e^v), writes {dt,r} float2
__global__ __launch_bounds__(256) void k_gdt(const float* __restrict__ bdt,
                                             const float* __restrict__ bdtb) {
    GEMM_DECL_SMEM();
    GEMM_THREAD_IDS();
    const int br = blockIdx.z;
    const int K = 64;
    const uint16_t* Ag = g_dtloH[br];
    const uint16_t* Bg = g_WdtH[br];
    const float* bias = br ? bdtb : bdt;
    const int m0 = blockIdx.y * 128, n0 = blockIdx.x * 128;
    const uint16_t* pA = Ag + (size_t)(m0 + arow) * K + aseg * 8;
    const uint16_t* pB = Bg + (size_t)(n0 + arow) * K + aseg * 8;
    const int NK = 4;
    GEMM_ACC_INIT();
    GEMM_MAINLOOP(pA, pB, NK);

    float* dst = g_dtr[br];
#pragma unroll
    for (int mt = 0; mt < 4; mt++) {
        int row = wm * 64 + mt * 16 + (lane >> 2);
#pragma unroll
        for (int nt = 0; nt < 4; nt++) {
            int col = wn * 32 + nt * 8 + (lane & 3) * 2;
            float b1 = bias[n0 + col], b2 = bias[n0 + col + 1];
#pragma unroll
            for (int half = 0; half < 2; half++) {
                int rr = m0 + row + half * 8;
                float v0 = acc[mt][nt][half * 2 + 0] + b1;
                float v1 = acc[mt][nt][half * 2 + 1] + b2;
                float e0 = __expf(v0), e1 = __expf(v1);
                float dt0 = (v0 > 15.f) ? v0 : log1pf(e0);
                float dt1 = (v1 > 15.f) ? v1 : log1pf(e1);
                float r0 = 1.f / (1.f + e0);
                float r1 = 1.f / (1.f + e1);
                *(float4*)(dst + ((size_t)rr * D_INNER + n0 + col) * 2) =
                    make_float4(dt0, r0, dt1, r1);
            }
        }
    }
}

// ---------------- conv: token-major, fp16 outputs ----------------
__global__ __launch_bounds__(256) void k_conv(const float* __restrict__ cw, const float* __restrict__ cb,
                                              const float* __restrict__ cwb, const float* __restrict__ cbb) {
    __shared__ float xs[38][33];
    const int tx = threadIdx.x, ty = threadIdx.y;
    const int tid = ty * 32 + tx;
    const int l0 = blockIdx.x * 32, d0 = blockIdx.y * 32;
    const int b = blockIdx.z;

    for (int lin = tid; lin < 38 * 32; lin += 256) {
        int r = lin >> 5, c = lin & 31;
        int l = l0 - 3 + r;
        xs[r][c] = (l >= 0 && l < L_SEQ) ? g_xz[((size_t)b * L_SEQ + l) * E2 + d0 + c] : 0.f;
    }
    __syncthreads();

    const int d = d0 + tx;
    float wf0 = cw[d * 4 + 0], wf1 = cw[d * 4 + 1], wf2 = cw[d * 4 + 2], wf3 = cw[d * 4 + 3];
    float wb0 = cwb[d * 4 + 0], wb1 = cwb[d * 4 + 1], wb2 = cwb[d * 4 + 2], wb3 = cwb[d * 4 + 3];
    float bf = cb[d], bbk = cbb[d];

#pragma unroll
    for (int i = 0; i < 4; i++) {
        int ll = ty + i * 8;
        float sf = bf + wf0 * xs[ll][tx] + wf1 * xs[ll + 1][tx] + wf2 * xs[ll + 2][tx] + wf3 * xs[ll + 3][tx];
        float sb = bbk + wb0 * xs[ll + 6][tx] + wb1 * xs[ll + 5][tx] + wb2 * xs[ll + 4][tx] + wb3 * xs[ll + 3][tx];
        size_t tf = (size_t)b * L_SEQ + l0 + ll;
        size_t tb = (size_t)b * L_SEQ + (L_SEQ - 1 - l0 - ll);
        g_xcT[0][tf * D_INNER + d] = h16(siluf(sf));
        g_xcT[1][tb * D_INNER + d] = h16(siluf(sb));
    }
}

// ---------------- zero g_xdbl ----------------
__global__ __launch_bounds__(256) void k_zero(float4* p, int n4) {
    int i = blockIdx.x * blockDim.x + threadIdx.x;
    if (i < n4) p[i] = make_float4(0.f, 0.f, 0.f, 0.f);
}

// ---------------- dt_lo transpose ----------------
__global__ __launch_bounds__(256) void k_dtloT() {
    __shared__ float s[48][65];
    const int tid = threadIdx.x;
    const int l0 = blockIdx.x * 64;
    const int b = blockIdx.y;
    const int br = blockIdx.z;
    const float* xd = g_xdbl[br] + ((size_t)b * XD) * L_SEQ;
    for (int lin = tid; lin < 48 * 64; lin += 256) {
        int r = lin >> 6, ll = lin & 63;
        s[r][ll] = xd[(size_t)r * L_SEQ + l0 + ll];
    }
    __syncthreads();
    uint16_t* dst = g_dtloH[br] + ((size_t)b * L_SEQ + l0) * 64;
    for (int lin = tid; lin < 64 * 64; lin += 256) {
        int ll = lin >> 6, r = lin & 63;
        dst[(size_t)ll * 64 + r] = (r < DR) ? h16(s[r][ll]) : (uint16_t)0;
    }
}

// ---------------- scan pass 1 (no exp in fast path) ----------------
__global__ __launch_bounds__(128) void k_scan1(const float* __restrict__ Alog, const float* __restrict__ Alogb) {
    const int tid = threadIdx.x;
    const int d = blockIdx.x * 128 + tid;
    const int chunk = blockIdx.y;
    const int zb = blockIdx.z;
    const int br = zb >> 1, b = zb & 1;
    const float* Al = br ? Alogb : Alog;
    float a[DS];
    int fast = 1;
#pragma unroll
    for (int n = 0; n < DS; n++) {
        a[n] = -expf(Al[d * DS + n]);
        fast &= (fabsf(a[n] + (float)(n + 1)) < 1e-4f * (float)(n + 1));
    }

    __shared__ float Bsh[CHL][DS + 1];
    const int l0 = chunk * CHL;
    const float* xd = g_xdbl[br] + (b * XD) * L_SEQ;
    for (int i = tid; i < CHL * DS; i += 128) {
        int n = i >> 7, t = i & (CHL - 1);
        Bsh[t][n] = xd[(DR + n) * L_SEQ + l0 + t];
    }
    __syncthreads();

    const float2* dtrp = (const float2*)g_dtr[br] + ((size_t)b * L_SEQ + l0) * D_INNER + d;
    const __half* xp = (const __half*)g_xcT[br] + ((size_t)b * L_SEQ + l0) * D_INNER + d;
    float h[DS];
#pragma unroll
    for (int n = 0; n < DS; n++) h[n] = 0.f;

    size_t base = ((size_t)(zb * D_INNER + d) * NCH + chunk) * DS;

    if (fast) {
        float Q = 1.f;
#pragma unroll 4
        for (int t = 0; t < CHL; t++) {
            float2 dr = dtrp[(size_t)t * D_INNER];
            float x = __half2float(xp[(size_t)t * D_INNER]);
            float dtx = dr.x * x;
            float r = dr.y;
            Q *= r;
            float p = 1.f;
#pragma unroll
            for (int n = 0; n < DS; n++) {
                p *= r;
                h[n] = fmaf(p, h[n], dtx * Bsh[t][n]);
            }
        }
        float Pc = 1.f;
#pragma unroll
        for (int n = 0; n < DS; n++) {
            Pc *= Q;
            g_hfin[base + n] = h[n];
            g_P[base + n] = Pc;
        }
    } else {
        float S = 0.f;
#pragma unroll 2
        for (int t = 0; t < CHL; t++) {
            float2 dr = dtrp[(size_t)t * D_INNER];
            float dt = dr.x;
            float x = __half2float(xp[(size_t)t * D_INNER]);
            float dtx = dt * x;
            S += dt;
#pragma unroll
            for (int n = 0; n < DS; n++) {
                float dA = __expf(dt * a[n]);
                h[n] = fmaf(dA, h[n], dtx * Bsh[t][n]);
            }
        }
#pragma unroll
        for (int n = 0; n < DS; n++) {
            g_hfin[base + n] = h[n];
            g_P[base + n] = __expf(a[n] * S);
        }
    }
}

// ---------------- scan pass 2 ----------------
__global__ void k_scan2() {
    int id = blockIdx.x * blockDim.x + threadIdx.x;
    if (id >= 2 * BSZ * D_INNER * DS) return;
    int n = id & 15;
    int rest = id >> 4;
    int d = rest % D_INNER;
    int zb = rest / D_INNER;
    size_t base = ((size_t)(zb * D_INNER + d)) * (NCH * DS) + n;
    float H = 0.f;
#pragma unroll
    for (int c = 0; c < NCH; c++) {
        g_Hinit[base + c * DS] = H;
        H = g_P[base + c * DS] * H + g_hfin[base + c * DS];
    }
}

// ---------------- scan pass 3 (no exp in fast path, precomputed silu(z)) ----------------
__global__ __launch_bounds__(128) void k_scan3(const float* __restrict__ Alog, const float* __restrict__ Alogb,
                                               const float* __restrict__ Dp, const float* __restrict__ Dpb) {
    const int tid = threadIdx.x;
    const int d = blockIdx.x * 128 + tid;
    const int chunk = blockIdx.y;
    const int zb = blockIdx.z;
    const int br = zb >> 1, b = zb & 1;
    const float* Al = br ? Alogb : Alog;
    float a[DS];
    int fast = 1;
#pragma unroll
    for (int n = 0; n < DS; n++) {
        a[n] = -expf(Al[d * DS + n]);
        fast &= (fabsf(a[n] + (float)(n + 1)) < 1e-4f * (float)(n + 1));
    }

    __shared__ float Bsh[CHL][DS + 1];
    __shared__ float Csh[CHL][DS + 1];
    const int l0 = chunk * CHL;
    const float* xd = g_xdbl[br] + (b * XD) * L_SEQ;
    for (int i = tid; i < CHL * DS; i += 128) {
        int n = i >> 7, t = i & (CHL - 1);
        Bsh[t][n] = xd[(DR + n) * L_SEQ + l0 + t];
        Csh[t][n] = xd[(DR + DS + n) * L_SEQ + l0 + t];
    }
    __syncthreads();

    size_t sbase = ((size_t)(zb * D_INNER + d) * NCH + chunk) * DS;
    float h[DS];
#pragma unroll
    for (int n = 0; n < DS; n++) h[n] = g_Hinit[sbase + n];
    float Dd = (br ? Dpb : Dp)[d];

    const float2* dtrp = (const float2*)g_dtr[br] + ((size_t)b * L_SEQ + l0) * D_INNER + d;
    const __half* xp = (const __half*)g_xcT[br] + ((size_t)b * L_SEQ + l0) * D_INNER + d;
    float* op = g_acc[br] + ((size_t)b * L_SEQ + l0) * D_INNER + d;
    const __half* szp;
    ptrdiff_t szstep;
    if (!br) {
        szp = (const __half*)g_szH + ((size_t)b * L_SEQ + l0) * D_INNER + d;
        szstep = D_INNER;
    } else {
        szp = (const __half*)g_szH + ((size_t)b * L_SEQ + (L_SEQ - 1 - l0)) * D_INNER + d;
        szstep = -(ptrdiff_t)D_INNER;
    }

    if (fast) {
#pragma unroll 4
        for (int t = 0; t < CHL; t++) {
            float2 dr = dtrp[(size_t)t * D_INNER];
            float x = __half2float(xp[(size_t)t * D_INNER]);
            float dtx = dr.x * x;
            float r = dr.y;
            float p = 1.f;
            float y = 0.f;
#pragma unroll
            for (int n = 0; n < DS; n++) {
                p *= r;
                h[n] = fmaf(p, h[n], dtx * Bsh[t][n]);
                y = fmaf(h[n], Csh[t][n], y);
            }
            float zv = __half2float(szp[(ptrdiff_t)t * szstep]);
            op[(size_t)t * D_INNER] = (y + Dd * x) * zv;
        }
    } else {
#pragma unroll 2
        for (int t = 0; t < CHL; t++) {
            float2 dr = dtrp[(size_t)t * D_INNER];
            float dt = dr.x;
            float x = __half2float(xp[(size_t)t * D_INNER]);
            float dtx = dt * x;
            float y = 0.f;
#pragma unroll
            for (int n = 0; n < DS; n++) {
                float dA = __expf(dt * a[n]);
                h[n] = fmaf(dA, h[n], dtx * Bsh[t][n]);
                y = fmaf(h[n], Csh[t][n], y);
            }
            float zv = __half2float(szp[(ptrdiff_t)t * szstep]);
            op[(size_t)t * D_INNER] = (y + Dd * x) * zv;
        }
    }
}

// ---------------- mid combine + fp16 pack ----------------
__global__ __launch_bounds__(256) void k_midT() {
    int i4 = blockIdx.x * blockDim.x + threadIdx.x;
    const int DV = D_INNER / 4;
    if (i4 >= NTOK * DV) return;
    int tok = i4 / DV;
    int d4 = i4 - tok * DV;
    int b = tok >> 11, l = tok & (L_SEQ - 1);
    int rtok = (b << 11) + (L_SEQ - 1 - l);
    float4 f = ((const float4*)g_acc[0])[i4];
    float4 r = ((const float4*)g_acc[1])[(size_t)rtok * DV + d4];
    ushort4 o;
    o.x = h16(0.5f * (f.x + r.x));
    o.y = h16(0.5f * (f.y + r.y));
    o.z = h16(0.5f * (f.z + r.z));
    o.w = h16(0.5f * (f.w + r.w));
    ((ushort4*)g_midH)[i4] = o;
}

// ---------------- launch ----------------
extern "C" void kernel_launch(void* const* d_in, const int* in_sizes, int n_in,
                              void* d_out, int out_size) {
    const float* hid  = (const float*)d_in[0];
    const float* Win  = (const float*)d_in[1];
    const float* cw   = (const float*)d_in[2];
    const float* cb   = (const float*)d_in[3];
    const float* cwb  = (const float*)d_in[4];
    const float* cbb  = (const float*)d_in[5];
    const float* Wx   = (const float*)d_in[6];
    const float* Wxb  = (const float*)d_in[7];
    const float* Wdt  = (const float*)d_in[8];
    const float* bdt  = (const float*)d_in[9];
    const float* Wdtb = (const float*)d_in[10];
    const float* bdtb = (const float*)d_in[11];
    const float* Alog = (const float*)d_in[12];
    const float* Alogb= (const float*)d_in[13];
    const float* Dp   = (const float*)d_in[14];
    const float* Dpb  = (const float*)d_in[15];
    const float* Wout = (const float*)d_in[16];
    float* out = (float*)d_out;

    uint16_t *hidH, *WinH, *WoutH, *midH;
    float *xzP, *xdblP;
    cudaGetSymbolAddress((void**)&hidH, g_hidH);
    cudaGetSymbolAddress((void**)&WinH, g_WinH);
    cudaGetSymbolAddress((void**)&WoutH, g_WoutH);
    cudaGetSymbolAddress((void**)&midH, g_midH);
    cudaGetSymbolAddress((void**)&xzP, g_xz);
    cudaGetSymbolAddress((void**)&xdblP, g_xdbl);

    const int n4a = NTOK * D_MODEL / 4, n4b = E2 * D_MODEL / 4, n4c = D_MODEL * D_INNER / 4;
    k_packh3<<<(n4a + n4b + n4c + 255) / 256, 256>>>((const float4*)hid, (ushort4*)hidH, n4a,
                                                     (const float4*)Win, (ushort4*)WinH, n4b,
                                                     (const float4*)Wout, (ushort4*)WoutH, n4c);
    k_packWx<<<(2 * 128 * D_INNER + 255) / 256, 256>>>(Wx, Wxb);
    k_packWdt<<<(2 * D_INNER * 64 + 255) / 256, 256>>>(Wdt, Wdtb);

    // xz[token][e] = hid @ Win^T
    k_mma<<<dim3(E2 / 128, NTOK / 128), 256>>>(hidH, WinH, xzP, D_MODEL, E2);

    // silu(z) precompute + conv
    k_silz<<<(NTOK * D_INNER / 4 + 255) / 256, 256>>>();
    k_conv<<<dim3(L_SEQ / 32, D_INNER / 32, BSZ), dim3(32, 8)>>>(cw, cb, cwb, cbb);

    // x_dbl = Wx @ xc
    k_zero<<<(2 * BSZ * XD * L_SEQ / 4 + 255) / 256, 256>>>((float4*)xdblP, 2 * BSZ * XD * L_SEQ / 4);
    k_gx<<<dim3(NTOK / 128, 1, 6), 256>>>();

    // dt = softplus(dt_lo @ Wdt^T + b); also r = exp(-dt)
    k_dtloT<<<dim3(L_SEQ / 64, BSZ, 2), 256>>>();
    k_gdt<<<dim3(D_INNER / 128, NTOK / 128, 2), 256>>>(bdt, bdtb);

    k_scan1<<<dim3(D_INNER / 128, NCH, 4), 128>>>(Alog, Alogb);
    k_scan2<<<(2 * BSZ * D_INNER * DS + 255) / 256, 256>>>();
    k_scan3<<<dim3(D_INNER / 128, NCH, 4), 128>>>(Alog, Alogb, Dp, Dpb);

    k_midT<<<(NTOK * D_INNER / 4 + 255) / 256, 256>>>();

    // out = mid @ Wout^T
    k_mma<<<dim3(D_MODEL / 128, NTOK / 128), 256>>>(midH, WoutH, out, D_INNER, D_MODEL);
}

// round 14
// speedup vs baseline: 1.1147x; 1.1147x over previous
#include <cuda_runtime.h>
#include <cuda_fp16.h>
#include <math.h>
#include <stdint.h>

#define L_SEQ 2048
#define D_MODEL 768
#define D_INNER 1536
#define E2 3072
#define DS 16
#define DR 48
#define XD 80
#define BSZ 2
#define NCH 16
#define CHL 128
#define NTOK 4096

// ---------------- scratch ----------------
__device__ float g_xz[NTOK * E2];                   // [token][e]
__device__ float g_xdbl[2][BSZ * XD * L_SEQ];       // [br][b][k][l]
__device__ float g_dtr[2][NTOK * D_INNER * 2];      // [tok][d] -> {dt, exp(-dt)}
__device__ float g_hfin[2 * BSZ * D_INNER * NCH * DS];
__device__ float g_P[2 * BSZ * D_INNER * NCH * DS];
__device__ float g_Hinit[2 * BSZ * D_INNER * NCH * DS];
__device__ float g_acc[2][NTOK * D_INNER];          // token-major

// fp16 planes
__device__ uint16_t g_hidH[NTOK * D_MODEL];
__device__ uint16_t g_WinH[E2 * D_MODEL];
__device__ uint16_t g_WoutH[D_MODEL * D_INNER];
__device__ uint16_t g_midH[NTOK * D_INNER];
__device__ uint16_t g_WxH[2][128 * D_INNER];
__device__ uint16_t g_WdtH[2][D_INNER * 64];
__device__ uint16_t g_xcT[2][NTOK * D_INNER];
__device__ uint16_t g_dtloH[2][NTOK * 64];
__device__ uint16_t g_szH[NTOK * D_INNER];          // silu(z) fp16

__device__ __forceinline__ float siluf(float v) {
    return v * (1.f / (1.f + __expf(-v)));
}
__device__ __forceinline__ uint16_t h16(float x) { return __half_as_ushort(__float2half(x)); }

// ---------------- pack kernels ----------------
__global__ __launch_bounds__(256) void k_packh3(const float4* __restrict__ s0, ushort4* __restrict__ d0, int n0,
                                                const float4* __restrict__ s1, ushort4* __restrict__ d1, int n1,
                                                const float4* __restrict__ s2, ushort4* __restrict__ d2, int n2) {
    int i = blockIdx.x * blockDim.x + threadIdx.x;
    const float4* s;
    ushort4* d;
    if (i < n0) { s = s0 + i; d = d0 + i; }
    else if (i < n0 + n1) { s = s1 + (i - n0); d = d1 + (i - n0); }
    else if (i < n0 + n1 + n2) { s = s2 + (i - n0 - n1); d = d2 + (i - n0 - n1); }
    else return;
    float4 v = *s;
    ushort4 o;
    o.x = h16(v.x); o.y = h16(v.y); o.z = h16(v.z); o.w = h16(v.w);
    *d = o;
}
__global__ __launch_bounds__(256) void k_packWx(const float* __restrict__ Wx, const float* __restrict__ Wxb) {
    int id = blockIdx.x * blockDim.x + threadIdx.x;
    if (id >= 2 * 128 * D_INNER) return;
    int br = id / (128 * D_INNER);
    int rem = id - br * 128 * D_INNER;
    int m = rem / D_INNER, k = rem - m * D_INNER;
    const float* W = br ? Wxb : Wx;
    g_WxH[br][rem] = (m < XD) ? h16(W[m * D_INNER + k]) : (uint16_t)0;
}
__global__ __launch_bounds__(256) void k_packWdt(const float* __restrict__ Wdt, const float* __restrict__ Wdtb) {
    int id = blockIdx.x * blockDim.x + threadIdx.x;
    if (id >= 2 * D_INNER * 64) return;
    int br = id / (D_INNER * 64);
    int rem = id - br * D_INNER * 64;
    int m = rem >> 6, k = rem & 63;
    const float* W = br ? Wdtb : Wdt;
    g_WdtH[br][rem] = (k < DR) ? h16(W[m * DR + k]) : (uint16_t)0;
}

// ---------------- silu(z) precompute ----------------
__global__ __launch_bounds__(256) void k_silz() {
    int i4 = blockIdx.x * blockDim.x + threadIdx.x;
    const int DV = D_INNER / 4;
    if (i4 >= NTOK * DV) return;
    int tok = i4 / DV;
    int d4 = i4 - tok * DV;
    float4 z = *(const float4*)(g_xz + (size_t)tok * E2 + D_INNER + d4 * 4);
    ushort4 o;
    o.x = h16(siluf(z.x)); o.y = h16(siluf(z.y));
    o.z = h16(siluf(z.z)); o.w = h16(siluf(z.w));
    ((ushort4*)g_szH)[i4] = o;
}

// ---------------- tensor-core GEMM: single-pass fp16, cp.async 4-stage pipeline ----------------
#define LDSM4(R, addr) \
    asm volatile("ldmatrix.sync.aligned.m8n8.x4.shared.b16 {%0,%1,%2,%3},[%4];" \
                 : "=r"(R[0]), "=r"(R[1]), "=r"(R[2]), "=r"(R[3]) : "r"(addr))

#define MMA16816(c, a, b0_, b1_) \
    asm volatile("mma.sync.aligned.m16n8k16.row.col.f32.f16.f16.f32 " \
                 "{%0,%1,%2,%3},{%4,%5,%6,%7},{%8,%9},{%0,%1,%2,%3};" \
                 : "+f"(c[0]), "+f"(c[1]), "+f"(c[2]), "+f"(c[3]) \
                 : "r"(a[0]), "r"(a[1]), "r"(a[2]), "r"(a[3]), "r"(b0_), "r"(b1_))

#define CPA16(dst, src) \
    asm volatile("cp.async.cg.shared.global [%0], [%1], 16;" :: "r"(dst), "l"(src))
#define CPCOMMIT() asm volatile("cp.async.commit_group;")
#define CPWAIT2()  asm volatile("cp.async.wait_group 2;")

#define GEMM_DECL_SMEM() \
    __shared__ __align__(16) uint16_t Ash[4][128][24]; \
    __shared__ __align__(16) uint16_t Bsh[4][128][24]

#define GEMM_THREAD_IDS() \
    const int tid = threadIdx.x; \
    const int lane = tid & 31, wid = tid >> 5; \
    const int wm = wid >> 2, wn = wid & 3; \
    const int arow = tid >> 1, aseg = tid & 1

#define GEMM_ACC_INIT() \
    float acc[4][4][4]; \
    _Pragma("unroll") for (int i = 0; i < 4; i++) \
    _Pragma("unroll") for (int j = 0; j < 4; j++) \
    _Pragma("unroll") for (int q = 0; q < 4; q++) acc[i][j][q] = 0.f

#define GEMM_MAINLOOP(pA, pB, NK) \
    const uint32_t stgb = 128 * 24 * 2; \
    uint32_t sA0 = (uint32_t)__cvta_generic_to_shared(&Ash[0][arow][aseg * 8]); \
    uint32_t sB0 = (uint32_t)__cvta_generic_to_shared(&Bsh[0][arow][aseg * 8]); \
    { \
        const int np_ = (NK) < 3 ? (NK) : 3; \
        for (int s = 0; s < np_; s++) { \
            CPA16(sA0 + s * stgb, (pA) + s * 16); \
            CPA16(sB0 + s * stgb, (pB) + s * 16); \
            CPCOMMIT(); \
        } \
        for (int s = np_; s < 3; s++) CPCOMMIT(); \
    } \
    const int lr = lane & 15, lc = lane >> 4; \
    const int brow = wn * 32 + (lane & 7) + ((lane >> 3) & 1) * 8; \
    for (int kt = 0; kt < (NK); ++kt) { \
        const int buf = kt & 3; \
        CPWAIT2(); \
        __syncthreads(); \
        uint32_t ah[4][4], bh[2][4]; \
        { \
            uint32_t aB = (uint32_t)__cvta_generic_to_shared(&Ash[buf][wm * 64 + lr][0]) + lc * 16; \
            _Pragma("unroll") for (int mt = 0; mt < 4; mt++) { \
                LDSM4(ah[mt], aB + mt * 16 * 48); \
            } \
            uint32_t bB = (uint32_t)__cvta_generic_to_shared(&Bsh[buf][brow][0]) + lc * 16; \
            _Pragma("unroll") for (int np = 0; np < 2; np++) { \
                LDSM4(bh[np], bB + np * 16 * 48); \
            } \
        } \
        _Pragma("unroll") for (int mt = 0; mt < 4; mt++) { \
            _Pragma("unroll") for (int nt = 0; nt < 4; nt++) { \
                const int np = nt >> 1, sel = nt & 1; \
                MMA16816(acc[mt][nt], ah[mt], bh[np][sel], bh[np][sel + 2]); \
            } \
        } \
        if (kt + 3 < (NK)) { \
            const int nb = (kt + 3) & 3; \
            CPA16(sA0 + nb * stgb, (pA) + (kt + 3) * 16); \
            CPA16(sB0 + nb * stgb, (pB) + (kt + 3) * 16); \
        } \
        CPCOMMIT(); \
    }

// Row-major C
__global__ __launch_bounds__(256, 2) void k_mma(const uint16_t* __restrict__ Ag,
                                                const uint16_t* __restrict__ Bg,
                                                float* __restrict__ Cg, int K, int ldc) {
    GEMM_DECL_SMEM();
    GEMM_THREAD_IDS();
    const int m0 = blockIdx.y * 128, n0 = blockIdx.x * 128;
    const uint16_t* pA = Ag + (size_t)(m0 + arow) * K + aseg * 8;
    const uint16_t* pB = Bg + (size_t)(n0 + arow) * K + aseg * 8;
    const int NK = K >> 4;
    GEMM_ACC_INIT();
    GEMM_MAINLOOP(pA, pB, NK);

    float* Cbase = Cg + (size_t)m0 * ldc + n0;
#pragma unroll
    for (int mt = 0; mt < 4; mt++) {
        int row = wm * 64 + mt * 16 + (lane >> 2);
#pragma unroll
        for (int nt = 0; nt < 4; nt++) {
            int col = wn * 32 + nt * 8 + (lane & 3) * 2;
            *(float2*)(Cbase + (size_t)row * ldc + col) = make_float2(acc[mt][nt][0], acc[mt][nt][1]);
            *(float2*)(Cbase + (size_t)(row + 8) * ldc + col) = make_float2(acc[mt][nt][2], acc[mt][nt][3]);
        }
    }
}

// x_dbl GEMM: split-K 3, atomic epilogue
__global__ __launch_bounds__(256, 2) void k_gx() {
    GEMM_DECL_SMEM();
    GEMM_THREAD_IDS();
    const int z = blockIdx.z;
    const int br = z / 3, ks = z - br * 3;
    const int k0 = ks * 512;
    const int K = D_INNER;
    const uint16_t* Ag = g_WxH[br];
    const uint16_t* Bg = g_xcT[br];
    const int n0 = blockIdx.x * 128;
    const uint16_t* pA = Ag + (size_t)arow * K + k0 + aseg * 8;
    const uint16_t* pB = Bg + (size_t)(n0 + arow) * K + k0 + aseg * 8;
    const int NK = 32;
    GEMM_ACC_INIT();
    GEMM_MAINLOOP(pA, pB, NK);

    const int b = n0 >> 11;
    const int l0c = n0 & (L_SEQ - 1);
    float* xd = g_xdbl[br] + ((size_t)b * XD) * L_SEQ + l0c;
#pragma unroll
    for (int mt = 0; mt < 4; mt++) {
        int row = wm * 64 + mt * 16 + (lane >> 2);
#pragma unroll
        for (int nt = 0; nt < 4; nt++) {
            int col = wn * 32 + nt * 8 + (lane & 3) * 2;
            if (row < XD) {
                atomicAdd(xd + (size_t)row * L_SEQ + col, acc[mt][nt][0]);
                atomicAdd(xd + (size_t)row * L_SEQ + col + 1, acc[mt][nt][1]);
            }
            if (row + 8 < XD) {
                atomicAdd(xd + (size_t)(row + 8) * L_SEQ + col, acc[mt][nt][2]);
                atomicAdd(xd + (size_t)(row + 8) * L_SEQ + col + 1, acc[mt][nt][3]);
            }
        }
    }
}

// dt GEMM: epilogue dt = softplus(v), r = 1/(1+e^v); writes {dt,r} float2
__global__ __launch_bounds__(256, 2) void k_gdt(const float* __restrict__ bdt,
                                                const float* __restrict__ bdtb) {
    GEMM_DECL_SMEM();
    GEMM_THREAD_IDS();
    const int br = blockIdx.z;
    const int K = 64;
    const uint16_t* Ag = g_dtloH[br];
    const uint16_t* Bg = g_WdtH[br];
    const float* bias = br ? bdtb : bdt;
    const int m0 = blockIdx.y * 128, n0 = blockIdx.x * 128;
    const uint16_t* pA = Ag + (size_t)(m0 + arow) * K + aseg * 8;
    const uint16_t* pB = Bg + (size_t)(n0 + arow) * K + aseg * 8;
    const int NK = 4;
    GEMM_ACC_INIT();
    GEMM_MAINLOOP(pA, pB, NK);

    float* dst = g_dtr[br];
#pragma unroll
    for (int mt = 0; mt < 4; mt++) {
        int row = wm * 64 + mt * 16 + (lane >> 2);
#pragma unroll
        for (int nt = 0; nt < 4; nt++) {
            int col = wn * 32 + nt * 8 + (lane & 3) * 2;
            float b1 = bias[n0 + col], b2 = bias[n0 + col + 1];
#pragma unroll
            for (int half = 0; half < 2; half++) {
                int rr = m0 + row + half * 8;
                float v0 = acc[mt][nt][half * 2 + 0] + b1;
                float v1 = acc[mt][nt][half * 2 + 1] + b2;
                float e0 = __expf(v0), e1 = __expf(v1);
                float dt0 = (v0 > 15.f) ? v0 : log1pf(e0);
                float dt1 = (v1 > 15.f) ? v1 : log1pf(e1);
                float r0 = 1.f / (1.f + e0);
                float r1 = 1.f / (1.f + e1);
                *(float4*)(dst + ((size_t)rr * D_INNER + n0 + col) * 2) =
                    make_float4(dt0, r0, dt1, r1);
            }
        }
    }
}

// ---------------- conv ----------------
__global__ __launch_bounds__(256) void k_conv(const float* __restrict__ cw, const float* __restrict__ cb,
                                              const float* __restrict__ cwb, const float* __restrict__ cbb) {
    __shared__ float xs[38][33];
    const int tx = threadIdx.x, ty = threadIdx.y;
    const int tid = ty * 32 + tx;
    const int l0 = blockIdx.x * 32, d0 = blockIdx.y * 32;
    const int b = blockIdx.z;

    for (int lin = tid; lin < 38 * 32; lin += 256) {
        int r = lin >> 5, c = lin & 31;
        int l = l0 - 3 + r;
        xs[r][c] = (l >= 0 && l < L_SEQ) ? g_xz[((size_t)b * L_SEQ + l) * E2 + d0 + c] : 0.f;
    }
    __syncthreads();

    const int d = d0 + tx;
    float wf0 = cw[d * 4 + 0], wf1 = cw[d * 4 + 1], wf2 = cw[d * 4 + 2], wf3 = cw[d * 4 + 3];
    float wb0 = cwb[d * 4 + 0], wb1 = cwb[d * 4 + 1], wb2 = cwb[d * 4 + 2], wb3 = cwb[d * 4 + 3];
    float bf = cb[d], bbk = cbb[d];

#pragma unroll
    for (int i = 0; i < 4; i++) {
        int ll = ty + i * 8;
        float sf = bf + wf0 * xs[ll][tx] + wf1 * xs[ll + 1][tx] + wf2 * xs[ll + 2][tx] + wf3 * xs[ll + 3][tx];
        float sb = bbk + wb0 * xs[ll + 6][tx] + wb1 * xs[ll + 5][tx] + wb2 * xs[ll + 4][tx] + wb3 * xs[ll + 3][tx];
        size_t tf = (size_t)b * L_SEQ + l0 + ll;
        size_t tb = (size_t)b * L_SEQ + (L_SEQ - 1 - l0 - ll);
        g_xcT[0][tf * D_INNER + d] = h16(siluf(sf));
        g_xcT[1][tb * D_INNER + d] = h16(siluf(sb));
    }
}

// ---------------- zero g_xdbl ----------------
__global__ __launch_bounds__(256) void k_zero(float4* p, int n4) {
    int i = blockIdx.x * blockDim.x + threadIdx.x;
    if (i < n4) p[i] = make_float4(0.f, 0.f, 0.f, 0.f);
}

// ---------------- dt_lo transpose ----------------
__global__ __launch_bounds__(256) void k_dtloT() {
    __shared__ float s[48][65];
    const int tid = threadIdx.x;
    const int l0 = blockIdx.x * 64;
    const int b = blockIdx.y;
    const int br = blockIdx.z;
    const float* xd = g_xdbl[br] + ((size_t)b * XD) * L_SEQ;
    for (int lin = tid; lin < 48 * 64; lin += 256) {
        int r = lin >> 6, ll = lin & 63;
        s[r][ll] = xd[(size_t)r * L_SEQ + l0 + ll];
    }
    __syncthreads();
    uint16_t* dst = g_dtloH[br] + ((size_t)b * L_SEQ + l0) * 64;
    for (int lin = tid; lin < 64 * 64; lin += 256) {
        int ll = lin >> 6, r = lin & 63;
        dst[(size_t)ll * 64 + r] = (r < DR) ? h16(s[r][ll]) : (uint16_t)0;
    }
}

// ---------------- scan pass 1 ----------------
__global__ __launch_bounds__(128) void k_scan1(const float* __restrict__ Alog, const float* __restrict__ Alogb) {
    const int tid = threadIdx.x;
    const int d = blockIdx.x * 128 + tid;
    const int chunk = blockIdx.y;
    const int zb = blockIdx.z;
    const int br = zb >> 1, b = zb & 1;
    const float* Al = br ? Alogb : Alog;
    float a[DS];
    int fast = 1;
#pragma unroll
    for (int n = 0; n < DS; n++) {
        a[n] = -expf(Al[d * DS + n]);
        fast &= (fabsf(a[n] + (float)(n + 1)) < 1e-4f * (float)(n + 1));
    }

    __shared__ float Bsh[CHL][DS + 1];
    const int l0 = chunk * CHL;
    const float* xd = g_xdbl[br] + (b * XD) * L_SEQ;
    for (int i = tid; i < CHL * DS; i += 128) {
        int n = i >> 7, t = i & (CHL - 1);
        Bsh[t][n] = xd[(DR + n) * L_SEQ + l0 + t];
    }
    __syncthreads();

    const float2* dtrp = (const float2*)g_dtr[br] + ((size_t)b * L_SEQ + l0) * D_INNER + d;
    const __half* xp = (const __half*)g_xcT[br] + ((size_t)b * L_SEQ + l0) * D_INNER + d;
    float h[DS];
#pragma unroll
    for (int n = 0; n < DS; n++) h[n] = 0.f;

    size_t base = ((size_t)(zb * D_INNER + d) * NCH + chunk) * DS;

    if (fast) {
        float Q = 1.f;
#pragma unroll 4
        for (int t = 0; t < CHL; t++) {
            float2 dr = dtrp[(size_t)t * D_INNER];
            float x = __half2float(xp[(size_t)t * D_INNER]);
            float dtx = dr.x * x;
            float r = dr.y;
            Q *= r;
            float p = 1.f;
#pragma unroll
            for (int n = 0; n < DS; n++) {
                p *= r;
                h[n] = fmaf(p, h[n], dtx * Bsh[t][n]);
            }
        }
        float Pc = 1.f;
#pragma unroll
        for (int n = 0; n < DS; n++) {
            Pc *= Q;
            g_hfin[base + n] = h[n];
            g_P[base + n] = Pc;
        }
    } else {
        float S = 0.f;
#pragma unroll 2
        for (int t = 0; t < CHL; t++) {
            float2 dr = dtrp[(size_t)t * D_INNER];
            float dt = dr.x;
            float x = __half2float(xp[(size_t)t * D_INNER]);
            float dtx = dt * x;
            S += dt;
#pragma unroll
            for (int n = 0; n < DS; n++) {
                float dA = __expf(dt * a[n]);
                h[n] = fmaf(dA, h[n], dtx * Bsh[t][n]);
            }
        }
#pragma unroll
        for (int n = 0; n < DS; n++) {
            g_hfin[base + n] = h[n];
            g_P[base + n] = __expf(a[n] * S);
        }
    }
}

// ---------------- scan pass 2 ----------------
__global__ void k_scan2() {
    int id = blockIdx.x * blockDim.x + threadIdx.x;
    if (id >= 2 * BSZ * D_INNER * DS) return;
    int n = id & 15;
    int rest = id >> 4;
    int d = rest % D_INNER;
    int zb = rest / D_INNER;
    size_t base = ((size_t)(zb * D_INNER + d)) * (NCH * DS) + n;
    float H = 0.f;
#pragma unroll
    for (int c = 0; c < NCH; c++) {
        g_Hinit[base + c * DS] = H;
        H = g_P[base + c * DS] * H + g_hfin[base + c * DS];
    }
}

// ---------------- scan pass 3 ----------------
__global__ __launch_bounds__(128) void k_scan3(const float* __restrict__ Alog, const float* __restrict__ Alogb,
                                               const float* __restrict__ Dp, const float* __restrict__ Dpb) {
    const int tid = threadIdx.x;
    const int d = blockIdx.x * 128 + tid;
    const int chunk = blockIdx.y;
    const int zb = blockIdx.z;
    const int br = zb >> 1, b = zb & 1;
    const float* Al = br ? Alogb : Alog;
    float a[DS];
    int fast = 1;
#pragma unroll
    for (int n = 0; n < DS; n++) {
        a[n] = -expf(Al[d * DS + n]);
        fast &= (fabsf(a[n] + (float)(n + 1)) < 1e-4f * (float)(n + 1));
    }

    __shared__ float Bsh[CHL][DS + 1];
    __shared__ float Csh[CHL][DS + 1];
    const int l0 = chunk * CHL;
    const float* xd = g_xdbl[br] + (b * XD) * L_SEQ;
    for (int i = tid; i < CHL * DS; i += 128) {
        int n = i >> 7, t = i & (CHL - 1);
        Bsh[t][n] = xd[(DR + n) * L_SEQ + l0 + t];
        Csh[t][n] = xd[(DR + DS + n) * L_SEQ + l0 + t];
    }
    __syncthreads();

    size_t sbase = ((size_t)(zb * D_INNER + d) * NCH + chunk) * DS;
    float h[DS];
#pragma unroll
    for (int n = 0; n < DS; n++) h[n] = g_Hinit[sbase + n];
    float Dd = (br ? Dpb : Dp)[d];

    const float2* dtrp = (const float2*)g_dtr[br] + ((size_t)b * L_SEQ + l0) * D_INNER + d;
    const __half* xp = (const __half*)g_xcT[br] + ((size_t)b * L_SEQ + l0) * D_INNER + d;
    float* op = g_acc[br] + ((size_t)b * L_SEQ + l0) * D_INNER + d;
    const __half* szp;
    ptrdiff_t szstep;
    if (!br) {
        szp = (const __half*)g_szH + ((size_t)b * L_SEQ + l0) * D_INNER + d;
        szstep = D_INNER;
    } else {
        szp = (const __half*)g_szH + ((size_t)b * L_SEQ + (L_SEQ - 1 - l0)) * D_INNER + d;
        szstep = -(ptrdiff_t)D_INNER;
    }

    if (fast) {
#pragma unroll 4
        for (int t = 0; t < CHL; t++) {
            float2 dr = dtrp[(size_t)t * D_INNER];
            float x = __half2float(xp[(size_t)t * D_INNER]);
            float dtx = dr.x * x;
            float r = dr.y;
            float p = 1.f;
            float y = 0.f;
#pragma unroll
            for (int n = 0; n < DS; n++) {
                p *= r;
                h[n] = fmaf(p, h[n], dtx * Bsh[t][n]);
                y = fmaf(h[n], Csh[t][n], y);
            }
            float zv = __half2float(szp[(ptrdiff_t)t * szstep]);
            op[(size_t)t * D_INNER] = (y + Dd * x) * zv;
        }
    } else {
#pragma unroll 2
        for (int t = 0; t < CHL; t++) {
            float2 dr = dtrp[(size_t)t * D_INNER];
            float dt = dr.x;
            float x = __half2float(xp[(size_t)t * D_INNER]);
            float dtx = dt * x;
            float y = 0.f;
#pragma unroll
            for (int n = 0; n < DS; n++) {
                float dA = __expf(dt * a[n]);
                h[n] = fmaf(dA, h[n], dtx * Bsh[t][n]);
                y = fmaf(h[n], Csh[t][n], y);
            }
            float zv = __half2float(szp[(ptrdiff_t)t * szstep]);
            op[(size_t)t * D_INNER] = (y + Dd * x) * zv;
        }
    }
}

// ---------------- mid combine + fp16 pack ----------------
__global__ __launch_bounds__(256) void k_midT() {
    int i4 = blockIdx.x * blockDim.x + threadIdx.x;
    const int DV = D_INNER / 4;
    if (i4 >= NTOK * DV) return;
    int tok = i4 / DV;
    int d4 = i4 - tok * DV;
    int b = tok >> 11, l = tok & (L_SEQ - 1);
    int rtok = (b << 11) + (L_SEQ - 1 - l);
    float4 f = ((const float4*)g_acc[0])[i4];
    float4 r = ((const float4*)g_acc[1])[(size_t)rtok * DV + d4];
    ushort4 o;
    o.x = h16(0.5f * (f.x + r.x));
    o.y = h16(0.5f * (f.y + r.y));
    o.z = h16(0.5f * (f.z + r.z));
    o.w = h16(0.5f * (f.w + r.w));
    ((ushort4*)g_midH)[i4] = o;
}

// ---------------- launch ----------------
extern "C" void kernel_launch(void* const* d_in, const int* in_sizes, int n_in,
                              void* d_out, int out_size) {
    const float* hid  = (const float*)d_in[0];
    const float* Win  = (const float*)d_in[1];
    const float* cw   = (const float*)d_in[2];
    const float* cb   = (const float*)d_in[3];
    const float* cwb  = (const float*)d_in[4];
    const float* cbb  = (const float*)d_in[5];
    const float* Wx   = (const float*)d_in[6];
    const float* Wxb  = (const float*)d_in[7];
    const float* Wdt  = (const float*)d_in[8];
    const float* bdt  = (const float*)d_in[9];
    const float* Wdtb = (const float*)d_in[10];
    const float* bdtb = (const float*)d_in[11];
    const float* Alog = (const float*)d_in[12];
    const float* Alogb= (const float*)d_in[13];
    const float* Dp   = (const float*)d_in[14];
    const float* Dpb  = (const float*)d_in[15];
    const float* Wout = (const float*)d_in[16];
    float* out = (float*)d_out;

    uint16_t *hidH, *WinH, *WoutH, *midH;
    float *xzP, *xdblP;
    cudaGetSymbolAddress((void**)&hidH, g_hidH);
    cudaGetSymbolAddress((void**)&WinH, g_WinH);
    cudaGetSymbolAddress((void**)&WoutH, g_WoutH);
    cudaGetSymbolAddress((void**)&midH, g_midH);
    cudaGetSymbolAddress((void**)&xzP, g_xz);
    cudaGetSymbolAddress((void**)&xdblP, g_xdbl);

    const int n4a = NTOK * D_MODEL / 4, n4b = E2 * D_MODEL / 4, n4c = D_MODEL * D_INNER / 4;
    k_packh3<<<(n4a + n4b + n4c + 255) / 256, 256>>>((const float4*)hid, (ushort4*)hidH, n4a,
                                                     (const float4*)Win, (ushort4*)WinH, n4b,
                                                     (const float4*)Wout, (ushort4*)WoutH, n4c);
    k_packWx<<<(2 * 128 * D_INNER + 255) / 256, 256>>>(Wx, Wxb);
    k_packWdt<<<(2 * D_INNER * 64 + 255) / 256, 256>>>(Wdt, Wdtb);

    // xz[token][e] = hid @ Win^T
    k_mma<<<dim3(E2 / 128, NTOK / 128), 256>>>(hidH, WinH, xzP, D_MODEL, E2);

    // silu(z) + conv
    k_silz<<<(NTOK * D_INNER / 4 + 255) / 256, 256>>>();
    k_conv<<<dim3(L_SEQ / 32, D_INNER / 32, BSZ), dim3(32, 8)>>>(cw, cb, cwb, cbb);

    // x_dbl = Wx @ xc
    k_zero<<<(2 * BSZ * XD * L_SEQ / 4 + 255) / 256, 256>>>((float4*)xdblP, 2 * BSZ * XD * L_SEQ / 4);
    k_gx<<<dim3(NTOK / 128, 1, 6), 256>>>();

    // dt = softplus(dt_lo @ Wdt^T + b); r = exp(-dt)
    k_dtloT<<<dim3(L_SEQ / 64, BSZ, 2), 256>>>();
    k_gdt<<<dim3(D_INNER / 128, NTOK / 128, 2), 256>>>(bdt, bdtb);

    k_scan1<<<dim3(D_INNER / 128, NCH, 4), 128>>>(Alog, Alogb);
    k_scan2<<<(2 * BSZ * D_INNER * DS + 255) / 256, 256>>>();
    k_scan3<<<dim3(D_INNER / 128, NCH, 4), 128>>>(Alog, Alogb, Dp, Dpb);

    k_midT<<<(NTOK * D_INNER / 4 + 255) / 256, 256>>>();

    // out = mid @ Wout^T
    k_mma<<<dim3(D_MODEL / 128, NTOK / 128), 256>>>(midH, WoutH, out, D_INNER, D_MODEL);
}